// round 6
// baseline (speedup 1.0000x reference)
#include <cuda_runtime.h>

#define HH 512
#define WW 512
#define KS 32
#define PD 16            // KS/2
#define RC 16            // rows per chunk; warp w scans S[w] and Q[w]
#define RPB 128          // output rows per block
#define NT 512           // one thread per real column
#define SPITCH 544       // f(c) = c + (c>>4) maps 0..511 -> 0..542; slot 543 = zero
#define ZSLOT 543
#define SMEM_FLOATS (2 * RC * SPITCH)

__device__ __forceinline__ float frsqrt(float v) {
    float r;
    asm("rsqrt.approx.f32 %0, %1;" : "=f"(r) : "f"(v));
    return r;
}

__global__ __launch_bounds__(NT, 3)
void localnorm_v6(const float* __restrict__ x, float* __restrict__ out) {
    extern __shared__ float smem[];
    float* sS = smem;                    // [RC][SPITCH] vertical sums of x   -> prefix
    float* sQ = smem + RC * SPITCH;      // [RC][SPITCH] vertical sums of x^2 -> prefix

    const int tid  = threadIdx.x;
    const int lane = tid & 31;
    const int wid  = tid >> 5;
    const int r0   = blockIdx.x * RPB;

    const float* __restrict__ X = x   + (size_t)blockIdx.y * (HH * WW);
    float* __restrict__       O = out + (size_t)blockIdx.y * (HH * WW);

    // zero the "P[-1]" slots once (never touched by phases A/B)
    if (tid < 2 * RC) {
        float* p = (tid < RC) ? sS : sQ;
        p[(tid & (RC - 1)) * SPITCH + ZSLOT] = 0.f;
    }

    // ---- init vertical window: rows r0-16 .. r0+15 (lower reflect only) ----
    float vs = 0.f, vq = 0.f;
    #pragma unroll
    for (int d = -PD; d < PD; d++) {
        int rr = abs(r0 + d);
        float v = X[(rr << 9) + tid];
        vs += v; vq = fmaf(v, v, vq);
    }

    const int fcol = tid + (tid >> 4);
    const float inv_n = 1.f / (float)(KS * KS);

    // ---- phase-C per-thread constants (oc == tid) ----
    const int oc  = tid;
    int hi = oc + 15; if (hi > 511) hi = 511;
    const int fhi = hi + (hi >> 4);
    const int lo  = oc - 17;
    const int flo = (lo >= 0) ? (lo + (lo >> 4)) : ZSLOT;     // P[-1] == 0
    const bool leftE  = (oc <= 15);
    const bool rightE = (oc >= 497);
    const int fle  = leftE  ? ((16 - oc) + ((16 - oc) >> 4)) : 0;
    const int fre2 = rightE ? ((1006 - oc) + ((1006 - oc) >> 4)) : 0;

    #pragma unroll 1
    for (int chunk = 0; chunk < RPB / RC; chunk++) {
        const int ibase = r0 + chunk * RC;

        // ---- phase A: emit RC rows of vertical sums; slide window ----
        #pragma unroll
        for (int rr = 0; rr < RC; rr++) {
            sS[rr * SPITCH + fcol] = vs;
            sQ[rr * SPITCH + fcol] = vq;
            int i  = ibase + rr;
            int ru = i + PD; ru = (ru < HH) ? ru : (2 * HH - 2 - ru);
            int rd = abs(i - PD);
            float va = X[(ru << 9) + tid];
            float vb = X[(rd << 9) + tid];
            vs += va - vb;
            vq = fmaf(va, va, fmaf(-vb, vb, vq));
        }
        __syncthreads();

        // ---- phase B: warp w scans S[w] and Q[w] (interleaved, 2x ILP) ----
        {
            float* VS = sS + wid * SPITCH + lane * 17;
            float* VQ = sQ + wid * SPITCH + lane * 17;
            float runS = 0.f, runQ = 0.f;
            #pragma unroll
            for (int k = 0; k < 16; k++) { runS += VS[k]; runQ += VQ[k]; }
            float totS = runS, totQ = runQ;
            #pragma unroll
            for (int s = 1; s < 32; s <<= 1) {
                float uS = __shfl_up_sync(0xffffffffu, totS, s);
                float uQ = __shfl_up_sync(0xffffffffu, totQ, s);
                if (lane >= s) { totS += uS; totQ += uQ; }
            }
            float accS = totS - runS;            // exclusive offsets
            float accQ = totQ - runQ;
            #pragma unroll
            for (int k = 0; k < 16; k++) {
                accS += VS[k];  VS[k] = accS;
                accQ += VQ[k];  VQ[k] = accQ;
            }
        }
        __syncthreads();

        // ---- phase C: box[oc] = P[hi]-P[lo] (+ edge terms); finalize ----
        const float* Xc = X + (ibase << 9) + tid;
        float*       Oc = O + (ibase << 9) + tid;
        #pragma unroll 4
        for (int rr = 0; rr < RC; rr++) {
            const float* pS = sS + rr * SPITCH;
            const float* pQ = sQ + rr * SPITCH;
            float bS = pS[fhi] - pS[flo];
            float bQ = pQ[fhi] - pQ[flo];
            if (leftE)  { bS += pS[fle] - pS[0];    bQ += pQ[fle] - pQ[0]; }
            if (rightE) { bS += pS[541] - pS[fre2]; bQ += pQ[541] - pQ[fre2]; }
            float mean = bS * inv_n;
            float msq  = bQ * inv_n;
            float xc   = Xc[rr << 9];
            float var  = fabsf(fmaf(-mean, mean, msq));
            float r    = (xc - mean) * frsqrt(var + 1e-20f);
            r = fminf(fmaxf(r, -6.f), 6.f);
            Oc[rr << 9] = r;
        }
        __syncthreads();
    }
}

extern "C" void kernel_launch(void* const* d_in, const int* in_sizes, int n_in,
                              void* d_out, int out_size) {
    const float* x = (const float*)d_in[0];
    float* out = (float*)d_out;
    const int n_img = in_sizes[0] / (HH * WW);    // 96
    const int smem_bytes = SMEM_FLOATS * (int)sizeof(float);   // 69632

    cudaFuncSetAttribute(localnorm_v6,
                         cudaFuncAttributeMaxDynamicSharedMemorySize, smem_bytes);

    dim3 grid(HH / RPB, n_img);                   // 4 x 96 = 384 blocks
    localnorm_v6<<<grid, NT, smem_bytes>>>(x, out);
}